// round 10
// baseline (speedup 1.0000x reference)
#include <cuda_runtime.h>
#include <cstdint>

// Problem constants (fixed shapes per reference)
#define NNODES   30000
#define RREL     8
#define NBASES   30
#define IN_DIM   256
#define Z_DIM    128
#define HID      256           // Z_DIM*2
#define NEDGES   480000        // N*16
#define NSEG     (NNODES*RREL) // 240000
#define KAGG     (RREL*256)    // 2048
#define SCAN_B   1024
#define NSCANB   ((NSEG + SCAN_B - 1) / SCAN_B)   // 235

// ---------------- scratch (device globals; referenced DIRECTLY by kernels) ---
__device__ __align__(16) float g_M  [(size_t)NNODES * RREL * 256];  // 245.76 MB
__device__ __align__(16) float g_Z1 [(size_t)NNODES * HID];
__device__ __align__(16) float g_W1 [(size_t)RREL * IN_DIM * HID];  // [2048, 256]
__device__ __align__(16) float g_W2 [(size_t)RREL * HID * Z_DIM];   // [2048, 128]
__device__ int   g_cnt [NSEG];
__device__ int   g_off [NSEG];      // exclusive prefix of cnt
__device__ int   g_fill[NSEG];      // running fill cursor for placement
__device__ int   g_src [NEDGES];
__device__ int   g_seg [NEDGES];
__device__ int   g_esrc[NEDGES];    // src ids sorted by segment (CSR payload)
__device__ int   g_bsum[256];
__device__ int   g_bpre[256];
__device__ int   g_is64;

// ---------------- dtype autodetect (int32 vs int64 edge arrays) --------------
__global__ void detect_dtype(const unsigned* __restrict__ et_words) {
    int is64 = 1;
    for (int i = 0; i < 64; ++i) {
        unsigned lo = et_words[2 * i];
        unsigned hi = et_words[2 * i + 1];
        if (hi != 0u || lo >= (unsigned)RREL) { is64 = 0; break; }
    }
    g_is64 = is64;
}

__global__ void zero_cnt() {
    int i = blockIdx.x * 256 + threadIdx.x;
    if (i < NSEG) g_cnt[i] = 0;
}

// edges -> int32 src/seg (dtype-agnostic), count edges per (dst, rel) segment.
__global__ void prep_edges(const void* __restrict__ ei_raw,
                           const void* __restrict__ et_raw) {
    int e = blockIdx.x * 256 + threadIdx.x;
    if (e >= NEDGES) return;
    int s, d, t;
    if (g_is64) {
        const long long* ei = (const long long*)ei_raw;
        const long long* et = (const long long*)et_raw;
        s = (int)ei[e]; d = (int)ei[NEDGES + e]; t = (int)et[e];
    } else {
        const int* ei = (const int*)ei_raw;
        const int* et = (const int*)et_raw;
        s = ei[e];      d = ei[NEDGES + e];      t = et[e];
    }
    s = min(max(s, 0), NNODES - 1);
    d = min(max(d, 0), NNODES - 1);
    t = min(max(t, 0), RREL - 1);
    g_src[e] = s;
    int g = d * RREL + t;
    g_seg[e] = g;
    atomicAdd(&g_cnt[g], 1);
}

// ---------------- two-level exclusive scan over g_cnt -------------------------
__global__ void scan_local() {
    __shared__ int sh[SCAN_B];
    int tid = threadIdx.x;
    int i = blockIdx.x * SCAN_B + tid;
    int v = (i < NSEG) ? g_cnt[i] : 0;
    sh[tid] = v;
    __syncthreads();
    for (int off = 1; off < SCAN_B; off <<= 1) {
        int t = 0;
        if (tid >= off) t = sh[tid - off];
        __syncthreads();
        if (tid >= off) sh[tid] += t;
        __syncthreads();
    }
    if (i < NSEG) g_off[i] = sh[tid] - v;            // exclusive
    if (tid == SCAN_B - 1) g_bsum[blockIdx.x] = sh[tid];
}

__global__ void scan_blocks() {   // single block, 256 threads, NSCANB<=256
    __shared__ int sh[256];
    int tid = threadIdx.x;
    int v = (tid < NSCANB) ? g_bsum[tid] : 0;
    sh[tid] = v;
    __syncthreads();
    for (int off = 1; off < 256; off <<= 1) {
        int t = 0;
        if (tid >= off) t = sh[tid - off];
        __syncthreads();
        if (tid >= off) sh[tid] += t;
        __syncthreads();
    }
    g_bpre[tid] = sh[tid] - v;                        // exclusive
}

__global__ void scan_add_fill() {
    int i = blockIdx.x * 256 + threadIdx.x;
    if (i >= NSEG) return;
    int o = g_off[i] + g_bpre[i >> 10];
    g_off[i] = o;
    g_fill[i] = o;
}

// Place edges into CSR order (order within a segment irrelevant for a sum).
__global__ void place_edges() {
    int e = blockIdx.x * 256 + threadIdx.x;
    if (e >= NEDGES) return;
    int pos = atomicAdd(&g_fill[g_seg[e]], 1);
    g_esrc[pos] = g_src[e];
}

// W[r, io] = sum_b comp[r,b] * bases[b, io]   (layer selects g_W1/g_W2)
__global__ void build_W(const float* __restrict__ bases,
                        const float* __restrict__ comp,
                        int IO, int layer) {
    float* W = (layer == 1) ? g_W1 : g_W2;
    __shared__ float sc[RREL * NBASES];
    if (threadIdx.x < RREL * NBASES) sc[threadIdx.x] = comp[threadIdx.x];
    __syncthreads();
    int io = blockIdx.x * 256 + threadIdx.x;
    if (io >= IO) return;
    float acc[RREL];
#pragma unroll
    for (int r = 0; r < RREL; ++r) acc[r] = 0.f;
#pragma unroll 5
    for (int b = 0; b < NBASES; ++b) {
        float bv = bases[(size_t)b * IO + io];
#pragma unroll
        for (int r = 0; r < RREL; ++r) acc[r] += sc[r * NBASES + b] * bv;
    }
#pragma unroll
    for (int r = 0; r < RREL; ++r) W[(size_t)r * IO + io] = acc[r];
}

// CSR gather: M[sg,:] = (1/max(cnt,1)) * sum_{e in seg} feat[esrc[e],:]
// 64 threads per segment, 4 segments per block; each M row written exactly once
// (empty segments write zeros -> no separate zeroing pass, no atomics).
__global__ void gather_segments(const float* __restrict__ x, int use_z1) {
    const float* feat = use_z1 ? g_Z1 : x;
    int sg = blockIdx.x * 4 + (threadIdx.x >> 6);
    int lane = threadIdx.x & 63;
    if (sg >= NSEG) return;
    int start = g_off[sg];
    int deg   = g_cnt[sg];
    float4 acc = make_float4(0.f, 0.f, 0.f, 0.f);
    for (int j = 0; j < deg; ++j) {
        int s = g_esrc[start + j];
        float4 v = *(const float4*)(feat + (size_t)s * 256 + lane * 4);
        acc.x += v.x; acc.y += v.y; acc.z += v.z; acc.w += v.w;
    }
    float sc = 1.0f / fmaxf((float)deg, 1.0f);
    acc.x *= sc; acc.y *= sc; acc.z *= sc; acc.w *= sc;
    *(float4*)(g_M + (size_t)sg * 256 + lane * 4) = acc;
}

// ---------------- fused dual-GEMM + bias + optional leaky-relu ---------------
// C[n,:] = g_M[n,:2048] @ W[2048,ncols] + A2[n,:256] @ root[256,ncols] + bias
#define BM 128
#define BN 128
#define BK 16
#define TM 8
#define TN 8

__global__ __launch_bounds__(256, 2)
void gemm_fused(int layer, const float* __restrict__ xin,
                const float* __restrict__ root, const float* __restrict__ bias,
                float* __restrict__ outp, int ncols)
{
    __shared__ float sA[BK][BM + 4];
    __shared__ float sB[BK][BN];

    const float* B1 = (layer == 1) ? g_W1 : g_W2;
    const float* A2 = (layer == 1) ? xin  : g_Z1;
    float*       C  = (layer == 1) ? g_Z1 : outp;
    const int leaky = (layer == 1);

    int tid = threadIdx.x;
    int tx = tid & 15;
    int ty = tid >> 4;
    int row0 = blockIdx.x * BM;
    int col0 = blockIdx.y * BN;

    float acc[TM][TN];
#pragma unroll
    for (int i = 0; i < TM; ++i)
#pragma unroll
        for (int j = 0; j < TN; ++j) acc[i][j] = 0.f;

    for (int phase = 0; phase < 2; ++phase) {
        const float* A = phase ? A2 : g_M;
        const float* B = phase ? root : B1;
        int K = phase ? 256 : KAGG;

        for (int k0 = 0; k0 < K; k0 += BK) {
#pragma unroll
            for (int i = 0; i < 2; ++i) {
                int idx = tid + i * 256;          // 0..511
                int ar  = idx >> 2;               // 0..127
                int ac  = (idx & 3) * 4;          // 0,4,8,12
                int grow = row0 + ar;
                float4 v = make_float4(0.f, 0.f, 0.f, 0.f);
                if (grow < NNODES)
                    v = *(const float4*)&A[(size_t)grow * K + k0 + ac];
                sA[ac + 0][ar] = v.x;
                sA[ac + 1][ar] = v.y;
                sA[ac + 2][ar] = v.z;
                sA[ac + 3][ar] = v.w;
            }
#pragma unroll
            for (int i = 0; i < 2; ++i) {
                int idx = tid + i * 256;
                int bk  = idx >> 5;               // 0..15
                int bc  = (idx & 31) * 4;         // 0..124
                *(float4*)&sB[bk][bc] =
                    *(const float4*)&B[(size_t)(k0 + bk) * ncols + col0 + bc];
            }
            __syncthreads();

#pragma unroll
            for (int k = 0; k < BK; ++k) {
                float4 a0 = *(const float4*)&sA[k][ty * TM];
                float4 a1 = *(const float4*)&sA[k][ty * TM + 4];
                float4 b0 = *(const float4*)&sB[k][tx * TN];
                float4 b1 = *(const float4*)&sB[k][tx * TN + 4];
                float ra[TM] = {a0.x, a0.y, a0.z, a0.w, a1.x, a1.y, a1.z, a1.w};
                float rb[TN] = {b0.x, b0.y, b0.z, b0.w, b1.x, b1.y, b1.z, b1.w};
#pragma unroll
                for (int i = 0; i < TM; ++i)
#pragma unroll
                    for (int j = 0; j < TN; ++j)
                        acc[i][j] += ra[i] * rb[j];
            }
            __syncthreads();
        }
    }

#pragma unroll
    for (int i = 0; i < TM; ++i) {
        int r = row0 + ty * TM + i;
        if (r >= NNODES) continue;
#pragma unroll
        for (int j = 0; j < TN; j += 4) {
            int c = col0 + tx * TN + j;
            float4 o;
            o.x = acc[i][j + 0] + bias[c + 0];
            o.y = acc[i][j + 1] + bias[c + 1];
            o.z = acc[i][j + 2] + bias[c + 2];
            o.w = acc[i][j + 3] + bias[c + 3];
            if (leaky) {
                o.x = o.x > 0.f ? o.x : 0.01f * o.x;
                o.y = o.y > 0.f ? o.y : 0.01f * o.y;
                o.z = o.z > 0.f ? o.z : 0.01f * o.z;
                o.w = o.w > 0.f ? o.w : 0.01f * o.w;
            }
            *(float4*)&C[(size_t)r * ncols + c] = o;
        }
    }
}

// ---------------- host: robust input binding by element count ----------------
static const void* find_in(void* const* d_in, const int* sz, int n_in,
                           int want, int occ, int fallback_idx) {
    int seen = 0;
    for (int i = 0; i < n_in; ++i) {
        if (sz[i] == want) {
            if (seen == occ) return d_in[i];
            ++seen;
        }
    }
    return d_in[fallback_idx];
}

extern "C" void kernel_launch(void* const* d_in, const int* in_sizes, int n_in,
                              void* d_out, int out_size) {
    const float* x      = (const float*)find_in(d_in, in_sizes, n_in, NNODES * IN_DIM,       0, 0);
    const void*  ei     =               find_in(d_in, in_sizes, n_in, 2 * NEDGES,            0, 1);
    const void*  et     =               find_in(d_in, in_sizes, n_in, NEDGES,                0, 2);
    const float* bases1 = (const float*)find_in(d_in, in_sizes, n_in, NBASES * IN_DIM * HID, 0, 3);
    const float* comp1  = (const float*)find_in(d_in, in_sizes, n_in, RREL * NBASES,         0, 4);
    const float* root1  = (const float*)find_in(d_in, in_sizes, n_in, IN_DIM * HID,          0, 5);
    const float* bias1  = (const float*)find_in(d_in, in_sizes, n_in, HID,                   0, 6);
    const float* bases2 = (const float*)find_in(d_in, in_sizes, n_in, NBASES * HID * Z_DIM,  0, 7);
    const float* comp2  = (const float*)find_in(d_in, in_sizes, n_in, RREL * NBASES,         1, 8);
    const float* root2  = (const float*)find_in(d_in, in_sizes, n_in, HID * Z_DIM,           0, 9);
    const float* bias2  = (const float*)find_in(d_in, in_sizes, n_in, Z_DIM,                 0, 10);
    float* out = (float*)d_out;

    // ---- prep: dtype, counts, CSR scan+placement, weights -------------------
    detect_dtype<<<1, 1>>>((const unsigned*)et);
    zero_cnt<<<(NSEG + 255) / 256, 256>>>();
    prep_edges<<<(NEDGES + 255) / 256, 256>>>(ei, et);
    scan_local<<<NSCANB, SCAN_B>>>();
    scan_blocks<<<1, 256>>>();
    scan_add_fill<<<(NSEG + 255) / 256, 256>>>();
    place_edges<<<(NEDGES + 255) / 256, 256>>>();
    build_W<<<(IN_DIM * HID + 255) / 256, 256>>>(bases1, comp1, IN_DIM * HID, 1);
    build_W<<<(HID * Z_DIM + 255) / 256, 256>>>(bases2, comp2, HID * Z_DIM, 2);

    // ---- layer 1: M = gather(x); Z1 = M@W1 + x@root1 + bias1; leaky ---------
    gather_segments<<<(NSEG + 3) / 4, 256>>>(x, /*use_z1=*/0);
    {
        dim3 grid((NNODES + BM - 1) / BM, HID / BN);
        gemm_fused<<<grid, 256>>>(1, x, root1, bias1, out, HID);
    }

    // ---- layer 2: M = gather(Z1); out = M@W2 + Z1@root2 + bias2 -------------
    gather_segments<<<(NSEG + 3) / 4, 256>>>(x, /*use_z1=*/1);
    {
        dim3 grid((NNODES + BM - 1) / BM, Z_DIM / BN);
        gemm_fused<<<grid, 256>>>(2, x, root2, bias2, out, Z_DIM);
    }
}